// round 1
// baseline (speedup 1.0000x reference)
#include <cuda_runtime.h>
#include <cuda_bf16.h>

// Problem constants
#define N_WIDTH     128
#define N_ORDER     4
#define N_NODES     513          // N_ELEMENTS*N_ORDER + 1
#define J           (N_ORDER + 1)  // 5
#define PLANE_ELEMS (N_WIDTH * N_NODES)   // 65664
#define PLANE_VEC   (PLANE_ELEMS / 4)     // 16416 (divisible: 65664/4)
#define TOTAL_VEC   (3 * PLANE_VEC)       // 49248

// Output: [3, 1, 128, 513] fp32 = buffer slice at `sample` from each of
// phi/dphi/ddphi, with 5 columns [nodes_l, nodes_l+4] overwritten by the
// freshly computed Lagrange basis values (identical for all 128 rows since
// x is a scalar broadcast).

__global__ void Phi_kernel(const float* __restrict__ x,
                           const float* __restrict__ phi,
                           const float* __restrict__ dphi,
                           const float* __restrict__ ddphi,
                           const int* __restrict__ sample_p,
                           float4* __restrict__ out)
{
    __shared__ float sv[3][J];   // [p | dp/delta | ddp/delta^2] x 5
    __shared__ int   s_nl;       // nodes_l (leftmost overwritten column)
    __shared__ int   s_sample;

    if (threadIdx.x == 0) {
        s_sample = sample_p[0];

        // x_shift = (N_NODES-1) * (x - 0) / (1 - 0) = 512 * x   (fp32, matches jax)
        float xv = x[0];
        float x_shift = 512.0f * xv;
        float fe = floorf(x_shift * 0.25f);       // /4 is exact in binary
        if (fe < 0.0f)   fe = 0.0f;
        if (fe > 127.0f) fe = 127.0f;
        int nl = ((int)fe) * N_ORDER;
        s_nl = nl;
        // xt = (x_shift - (nl + 2)) / 2
        float xt = (x_shift - (float)nl - 2.0f) * 0.5f;

        // Lagrange nodes on [-1,1], J=5
        const float t[J] = {-1.0f, -0.5f, 0.0f, 0.5f, 1.0f};
        float inv[J][J];
        float ratio[J][J];
        #pragma unroll
        for (int j = 0; j < J; j++) {
            #pragma unroll
            for (int m = 0; m < J; m++) {
                if (j == m) { inv[j][m] = 0.0f; ratio[j][m] = 1.0f; }
                else {
                    float d = t[j] - t[m];
                    inv[j][m]   = 1.0f / d;
                    ratio[j][m] = (xt - t[m]) / d;
                }
            }
        }

        const float inv_delta = 256.0f;   // delta = 0.5*4*(1-0)/512 = 1/256

        #pragma unroll
        for (int j = 0; j < J; j++) {
            // p_j = prod_m ratio[j][m]
            float p = 1.0f;
            #pragma unroll
            for (int m = 0; m < J; m++) p *= ratio[j][m];

            float dp = 0.0f, ddp = 0.0f;
            #pragma unroll
            for (int i = 0; i < J; i++) {
                if (i == j) continue;
                // prod over m != i,j
                float pr = 1.0f;
                #pragma unroll
                for (int m = 0; m < J; m++)
                    if (m != i && m != j) pr *= ratio[j][m];
                dp += inv[j][i] * pr;

                float s = 0.0f;
                #pragma unroll
                for (int m = 0; m < J; m++) {
                    if (m == i || m == j) continue;
                    float pr2 = 1.0f;
                    #pragma unroll
                    for (int n = 0; n < J; n++)
                        if (n != i && n != j && n != m) pr2 *= ratio[j][n];
                    s += inv[j][m] * pr2;
                }
                ddp += inv[j][i] * s;
            }

            sv[0][j] = p;
            sv[1][j] = dp * inv_delta;
            sv[2][j] = ddp * inv_delta * inv_delta;
        }
    }
    __syncthreads();

    int vidx = blockIdx.x * blockDim.x + threadIdx.x;
    if (vidx >= TOTAL_VEC) return;

    int plane = vidx / PLANE_VEC;            // 0=phi, 1=dphi, 2=ddphi
    int v     = vidx - plane * PLANE_VEC;    // float4 index within plane

    const float* srcf = (plane == 0) ? phi : (plane == 1) ? dphi : ddphi;
    const float4* src = (const float4*)srcf;

    float4 val = src[(size_t)s_sample * PLANE_VEC + v];

    int e  = v * 4;                 // element index within plane
    int c0 = e % N_NODES;           // column of first lane
    float* vp = (float*)&val;
    int nl = s_nl;
    #pragma unroll
    for (int k = 0; k < 4; k++) {
        int c = c0 + k;
        if (c >= N_NODES) c -= N_NODES;    // crossed into next row
        int d = c - nl;
        if ((unsigned)d < (unsigned)J) vp[k] = sv[plane][d];
    }

    out[vidx] = val;
}

extern "C" void kernel_launch(void* const* d_in, const int* in_sizes, int n_in,
                              void* d_out, int out_size) {
    const float* x       = (const float*)d_in[0];
    const float* phi     = (const float*)d_in[1];
    const float* dphi    = (const float*)d_in[2];
    const float* ddphi   = (const float*)d_in[3];
    const int*   sample  = (const int*)d_in[4];
    // d_in[5] = epoch (unused)
    float4* out = (float4*)d_out;

    const int threads = 256;
    const int blocks  = (TOTAL_VEC + threads - 1) / threads;  // 193
    Phi_kernel<<<blocks, threads>>>(x, phi, dphi, ddphi, sample, out);
}